// round 3
// baseline (speedup 1.0000x reference)
#include <cuda_runtime.h>
#include <math.h>

#define NB   32
#define CC   256
#define C4   64
#define LL   6
#define TT   64
#define VV   25
#define EPS  1e-5f
#define SLOPE 0.2f
#define NPAIR 45

// scratch (no cudaMalloc allowed)
__device__ float g_xt[NB * CC * LL * VV];     // [n][c][l][v]
__device__ float g_gate[NB * CC * LL];        // [n][c][l]

// flattened (layer, joint) pairs for the hierarchy means
__constant__ int c_pv[NPAIR] = {
    1,0,20,
    0,20,12,16,2,4,8,
    12,16,2,4,8,13,17,3,5,9,
    13,17,3,5,9,14,18,6,10,
    14,18,6,10,15,19,7,11,
    15,19,7,11,21,22,23,24};
__constant__ int c_pl[NPAIR] = {
    0,0,0,
    1,1,1,1,1,1,1,
    2,2,2,2,2,2,2,2,2,2,
    3,3,3,3,3,3,3,3,3,
    4,4,4,4,4,4,4,4,
    5,5,5,5,5,5,5,5};
__constant__ int c_off[LL + 1] = {0,3,10,20,29,37,45};
__constant__ float c_inv_cnt[LL] = {1.f/3.f, 1.f/7.f, 1.f/10.f, 1.f/9.f, 1.f/8.f, 1.f/8.f};

// ---------------------------------------------------------------------------
// Kernel 1: x_t[n,c,l,v] = max_t x[n,c,l,t,v]
// one block per (n,c,l); 1600 floats loaded as 400 float4 into smem.
// ---------------------------------------------------------------------------
__global__ __launch_bounds__(128) void k_tmax(const float* __restrict__ x) {
    __shared__ float4 tile4[400];
    float* tile = reinterpret_cast<float*>(tile4);
    const int b = blockIdx.x;                 // (n*C + c)*L + l
    const float4* xb = reinterpret_cast<const float4*>(x) + (size_t)b * 400;
    int tid = threadIdx.x;
    #pragma unroll
    for (int i = 0; i < 3; i++) tile4[tid + i * 128] = xb[tid + i * 128];
    if (tid < 16) tile4[tid + 384] = xb[tid + 384];
    __syncthreads();
    if (tid < VV) {
        float m = tile[tid];
        #pragma unroll
        for (int t = 1; t < TT; t++) m = fmaxf(m, tile[t * VV + tid]);
        g_xt[(size_t)b * VV + tid] = m;
    }
}

// ---------------------------------------------------------------------------
// Kernel 2: entire middle pipeline, one block per sample n, 256 threads.
// ---------------------------------------------------------------------------
__global__ __launch_bounds__(256) void k_middle(
    const float* __restrict__ W_down, const float* __restrict__ b_down,
    const float* __restrict__ g_down, const float* __restrict__ be_down,
    const float* __restrict__ m_down, const float* __restrict__ v_down,
    const float* __restrict__ W_edge, const float* __restrict__ g_edge,
    const float* __restrict__ be_edge, const float* __restrict__ m_edge,
    const float* __restrict__ v_edge, const float* __restrict__ W_agg,
    const float* __restrict__ b_agg) {
    const int n = blockIdx.x;
    const int t = threadIdx.x;

    __shared__ float sh_h[NPAIR][C4];
    __shared__ float sh_s[C4][LL];
    __shared__ float sh_G[LL * LL];
    __shared__ int   sh_idx[LL][3];
    __shared__ float sh_e[C4][LL];

    // ---- Phase A: h[pair][o] = relu(bn(W_down @ x_t + b))  (45 pairs) ----
    {
        const int o = t & 63;
        const float gs = g_down[o] * rsqrtf(v_down[o] + EPS);
        const float sh = be_down[o] - m_down[o] * gs;
        const float bd = b_down[o];
        const float* wr = W_down + o * CC;
        for (int pair = (t >> 6); pair < NPAIR; pair += 4) {
            const int l = c_pl[pair], v = c_pv[pair];
            const float* xp = g_xt + ((size_t)n * CC * LL + l) * VV + v;
            float a0 = 0.f, a1 = 0.f, a2 = 0.f, a3 = 0.f;
            #pragma unroll 4
            for (int c = 0; c < CC; c += 4) {
                a0 += wr[c]     * xp[(c)     * (LL * VV)];
                a1 += wr[c + 1] * xp[(c + 1) * (LL * VV)];
                a2 += wr[c + 2] * xp[(c + 2) * (LL * VV)];
                a3 += wr[c + 3] * xp[(c + 3) * (LL * VV)];
            }
            float y = ((a0 + a1) + (a2 + a3)) + bd;
            y = y * gs + sh;
            sh_h[pair][o] = fmaxf(y, 0.f);
        }
    }
    __syncthreads();

    // ---- Phase B: s[o][l] = mean over pairs of layer l ----
    if (t < C4) {
        #pragma unroll
        for (int l = 0; l < LL; l++) {
            float acc = 0.f;
            for (int p = c_off[l]; p < c_off[l + 1]; p++) acc += sh_h[p][t];
            sh_s[t][l] = acc * c_inv_cnt[l];
        }
    }
    __syncthreads();

    // ---- Phase C: Gram matrix G[i][j] = <s_i, s_j> ----
    if (t < LL * LL) {
        const int i = t / LL, j = t % LL;
        float acc = 0.f;
        #pragma unroll 8
        for (int o = 0; o < C4; o++) acc += sh_s[o][i] * sh_s[o][j];
        sh_G[t] = acc;
    }
    __syncthreads();

    // ---- Phase D: top-3 neighbors by -||si-sj||^2 (stable tie-break) ----
    if (t < LL) {
        float d[LL];
        bool used[LL];
        const float sqi = sh_G[t * LL + t];
        #pragma unroll
        for (int j = 0; j < LL; j++) {
            d[j] = 2.f * sh_G[t * LL + j] - sqi - sh_G[j * LL + j];
            used[j] = false;
        }
        #pragma unroll
        for (int k = 0; k < 3; k++) {
            float best = -INFINITY; int bi = 0;
            #pragma unroll
            for (int j = 0; j < LL; j++)
                if (!used[j] && d[j] > best) { best = d[j]; bi = j; }
            used[bi] = true;
            sh_idx[t][k] = bi;
        }
    }
    __syncthreads();

    // ---- Phase E: EdgeConv + BN + leaky + max over k -> e[o][l] ----
    for (int item = t; item < LL * C4; item += 256) {
        const int o = item & 63;
        const int l = item >> 6;
        const float* w1 = W_edge + o * (2 * C4);
        const float* w2 = w1 + C4;
        const int n0 = sh_idx[l][0], n1 = sh_idx[l][1], n2 = sh_idx[l][2];
        float base = 0.f, a0 = 0.f, a1 = 0.f, a2 = 0.f;
        #pragma unroll 4
        for (int c = 0; c < C4; c++) {
            const float w = w1[c];
            const float sl = sh_s[c][l];
            base += (w2[c] - w) * sl;
            a0 += w * sh_s[c][n0];
            a1 += w * sh_s[c][n1];
            a2 += w * sh_s[c][n2];
        }
        const float gs = g_edge[o] * rsqrtf(v_edge[o] + EPS);
        const float shb = be_edge[o] - m_edge[o] * gs;
        float m = -INFINITY;
        float ys[3] = {a0 + base, a1 + base, a2 + base};
        #pragma unroll
        for (int k = 0; k < 3; k++) {
            float y = ys[k] * gs + shb;
            y = fmaxf(y, 0.f) + SLOPE * fminf(y, 0.f);   // leaky relu
            m = fmaxf(m, y);
        }
        sh_e[o][l] = m;
    }
    __syncthreads();

    // ---- Phase F: att = W_agg @ e + b_agg ; gate = sigmoid ----
    {
        const int oc = t;                      // 256 threads == C outputs
        float a[LL];
        const float bb = b_agg[oc];
        #pragma unroll
        for (int l = 0; l < LL; l++) a[l] = bb;
        const float* wr = W_agg + oc * C4;
        #pragma unroll 4
        for (int c = 0; c < C4; c++) {
            const float w = wr[c];
            #pragma unroll
            for (int l = 0; l < LL; l++) a[l] += w * sh_e[c][l];
        }
        float* gp = g_gate + ((size_t)n * CC + oc) * LL;
        #pragma unroll
        for (int l = 0; l < LL; l++)
            gp[l] = 1.f / (1.f + expf(-a[l]));
    }
}

// ---------------------------------------------------------------------------
// Kernel 3: out[n,c,t,v] = sum_l x[n,c,l,t,v] * gate[n,c,l]   (float4)
// ---------------------------------------------------------------------------
__global__ __launch_bounds__(256) void k_gatesum(const float* __restrict__ x,
                                                 float* __restrict__ out) {
    const int gid = blockIdx.x * 256 + threadIdx.x;     // [0, 32*256*400)
    const int tv4 = gid % 400;
    const int nc  = gid / 400;
    const float4* xb = reinterpret_cast<const float4*>(x) + (size_t)nc * (LL * 400) + tv4;
    const float* gp = g_gate + (size_t)nc * LL;
    float4 acc = make_float4(0.f, 0.f, 0.f, 0.f);
    #pragma unroll
    for (int l = 0; l < LL; l++) {
        const float g = gp[l];
        const float4 xv = xb[l * 400];
        acc.x += xv.x * g; acc.y += xv.y * g;
        acc.z += xv.z * g; acc.w += xv.w * g;
    }
    reinterpret_cast<float4*>(out)[(size_t)nc * 400 + tv4] = acc;
}

// ---------------------------------------------------------------------------
extern "C" void kernel_launch(void* const* d_in, const int* in_sizes, int n_in,
                              void* d_out, int out_size) {
    const float* x       = (const float*)d_in[0];
    const float* W_down  = (const float*)d_in[1];
    const float* b_down  = (const float*)d_in[2];
    const float* g_down  = (const float*)d_in[3];
    const float* be_down = (const float*)d_in[4];
    const float* m_down  = (const float*)d_in[5];
    const float* v_down  = (const float*)d_in[6];
    const float* W_edge  = (const float*)d_in[7];
    const float* g_edge  = (const float*)d_in[8];
    const float* be_edge = (const float*)d_in[9];
    const float* m_edge  = (const float*)d_in[10];
    const float* v_edge  = (const float*)d_in[11];
    const float* W_agg   = (const float*)d_in[12];
    const float* b_agg   = (const float*)d_in[13];
    float* out = (float*)d_out;

    k_tmax<<<NB * CC * LL, 128>>>(x);
    k_middle<<<NB, 256>>>(W_down, b_down, g_down, be_down, m_down, v_down,
                          W_edge, g_edge, be_edge, m_edge, v_edge, W_agg, b_agg);
    k_gatesum<<<(NB * CC * 400) / 256, 256>>>(x, out);
}

// round 6
// speedup vs baseline: 3.5215x; 3.5215x over previous
#include <cuda_runtime.h>
#include <math.h>

#define NB   32
#define CC   256
#define C4   64
#define LL   6
#define TT   64
#define VV   25
#define EPS  1e-5f
#define SLOPE 0.2f
#define NPAIR 45

// scratch (no cudaMalloc allowed)
__device__ float g_xt[NB * LL * VV * CC];     // [n][l][v][c]  (c contiguous)
__device__ float g_s[NB * C4 * LL];           // [n][o][l]
__device__ float g_gate[NB * CC * LL];        // [n][c][l]

// flattened (layer, joint) pairs for the hierarchy means
__constant__ int c_pv[NPAIR] = {
    1,0,20,
    0,20,12,16,2,4,8,
    12,16,2,4,8,13,17,3,5,9,
    13,17,3,5,9,14,18,6,10,
    14,18,6,10,15,19,7,11,
    15,19,7,11,21,22,23,24};
__constant__ int c_off[LL + 1] = {0,3,10,20,29,37,45};
__constant__ float c_inv_cnt[LL] = {1.f/3.f, 1.f/7.f, 1.f/10.f, 1.f/9.f, 1.f/8.f, 1.f/8.f};

// ---------------------------------------------------------------------------
// Kernel 1: x_t = max_t x  -> stored transposed as [n][l][v][c]
// one block per (n,c,l); 1600 floats loaded as 400 float4 into smem.
// ---------------------------------------------------------------------------
__global__ __launch_bounds__(128) void k_tmax(const float* __restrict__ x) {
    __shared__ float4 tile4[400];
    float* tile = reinterpret_cast<float*>(tile4);
    const int b = blockIdx.x;                 // (n*C + c)*L + l
    const float4* xb = reinterpret_cast<const float4*>(x) + (size_t)b * 400;
    const int tid = threadIdx.x;
    #pragma unroll
    for (int i = 0; i < 3; i++) tile4[tid + i * 128] = xb[tid + i * 128];
    if (tid < 16) tile4[tid + 384] = xb[tid + 384];
    __syncthreads();
    if (tid < VV) {
        float m = tile[tid];
        #pragma unroll
        for (int t = 1; t < TT; t++) m = fmaxf(m, tile[t * VV + tid]);
        const int l = b % LL;
        const int nc = b / LL;
        const int c = nc % CC;
        const int n = nc / CC;
        g_xt[(((size_t)n * LL + l) * VV + tid) * CC + c] = m;
    }
}

// ---------------------------------------------------------------------------
// Kernel 2: s[n][o][l] = mean_v relu(bn(W_down @ x_t + b))
// grid = NB*LL blocks; smem-tiled over C in 4 chunks of 64.
// 256 threads = 64 outputs x 4 joint-groups.
// ---------------------------------------------------------------------------
__global__ __launch_bounds__(256) void k_s(
    const float* __restrict__ W_down, const float* __restrict__ b_down,
    const float* __restrict__ g_down, const float* __restrict__ be_down,
    const float* __restrict__ m_down, const float* __restrict__ v_down) {
    const int n = blockIdx.x / LL;
    const int l = blockIdx.x % LL;
    const int p0 = c_off[l];
    const int cnt = c_off[l + 1] - p0;        // 3..10 joints in this layer

    __shared__ float sh_W[64][65];
    __shared__ float sh_X[10][64];
    __shared__ float sh_hs[4][64];

    const int t = threadIdx.x;
    const int o = t & 63;
    const int g = t >> 6;

    float acc[3] = {0.f, 0.f, 0.f};
    const float* xbase = g_xt + ((size_t)(n * LL + l) * VV) * CC;

    #pragma unroll
    for (int ch = 0; ch < 4; ch++) {
        // load W chunk: 64 rows x 64 cols (as float4), coalesced
        for (int idx = t; idx < 64 * 16; idx += 256) {
            const int ro = idx >> 4, c4 = idx & 15;
            const float4 w = *reinterpret_cast<const float4*>(
                W_down + ro * CC + ch * 64 + c4 * 4);
            sh_W[ro][c4 * 4 + 0] = w.x; sh_W[ro][c4 * 4 + 1] = w.y;
            sh_W[ro][c4 * 4 + 2] = w.z; sh_W[ro][c4 * 4 + 3] = w.w;
        }
        // load X chunk: cnt rows x 64 cols
        for (int idx = t; idx < cnt * 16; idx += 256) {
            const int rv = idx >> 4, c4 = idx & 15;
            const int v = c_pv[p0 + rv];
            const float4 xv = *reinterpret_cast<const float4*>(
                xbase + (size_t)v * CC + ch * 64 + c4 * 4);
            sh_X[rv][c4 * 4 + 0] = xv.x; sh_X[rv][c4 * 4 + 1] = xv.y;
            sh_X[rv][c4 * 4 + 2] = xv.z; sh_X[rv][c4 * 4 + 3] = xv.w;
        }
        __syncthreads();
        #pragma unroll
        for (int jg = 0; jg < 3; jg++) {
            const int p = g + jg * 4;
            if (p < cnt) {
                float a = 0.f;
                #pragma unroll
                for (int cc = 0; cc < 64; cc++) a += sh_W[o][cc] * sh_X[p][cc];
                acc[jg] += a;
            }
        }
        __syncthreads();
    }

    // BN + ReLU per (o, joint), then partial sum over this thread's joints
    const float gs  = g_down[o] * rsqrtf(v_down[o] + EPS);
    const float shb = be_down[o] - m_down[o] * gs;
    const float bd  = b_down[o];
    float ssum = 0.f;
    #pragma unroll
    for (int jg = 0; jg < 3; jg++) {
        if (g + jg * 4 < cnt) {
            float y = (acc[jg] + bd) * gs + shb;
            ssum += fmaxf(y, 0.f);
        }
    }
    sh_hs[g][o] = ssum;
    __syncthreads();
    if (t < 64) {
        const float s = (sh_hs[0][t] + sh_hs[1][t] + sh_hs[2][t] + sh_hs[3][t])
                        * c_inv_cnt[l];
        g_s[((size_t)n * C4 + t) * LL + l] = s;
    }
}

// ---------------------------------------------------------------------------
// Kernel 3: knn + EdgeConv + aggregate + sigmoid gate. One block per sample.
// ---------------------------------------------------------------------------
__global__ __launch_bounds__(256) void k_mid(
    const float* __restrict__ W_edge, const float* __restrict__ g_edge,
    const float* __restrict__ be_edge, const float* __restrict__ m_edge,
    const float* __restrict__ v_edge, const float* __restrict__ W_agg,
    const float* __restrict__ b_agg) {
    const int n = blockIdx.x;
    const int t = threadIdx.x;

    __shared__ float sh_s[C4][LL];
    __shared__ float sh_G[LL * LL];
    __shared__ int   sh_idx[LL][3];
    __shared__ float sh_e[C4][LL];

    for (int i = t; i < C4 * LL; i += 256)
        sh_s[i / LL][i % LL] = g_s[(size_t)n * C4 * LL + i];
    __syncthreads();

    // Gram matrix
    if (t < LL * LL) {
        const int i = t / LL, j = t % LL;
        float acc = 0.f;
        #pragma unroll 8
        for (int o = 0; o < C4; o++) acc += sh_s[o][i] * sh_s[o][j];
        sh_G[t] = acc;
    }
    __syncthreads();

    // top-3 neighbors by -||si-sj||^2 (stable tie-break matching lax.top_k)
    if (t < LL) {
        float d[LL];
        bool used[LL];
        const float sqi = sh_G[t * LL + t];
        #pragma unroll
        for (int j = 0; j < LL; j++) {
            d[j] = 2.f * sh_G[t * LL + j] - sqi - sh_G[j * LL + j];
            used[j] = false;
        }
        #pragma unroll
        for (int k = 0; k < 3; k++) {
            float best = -INFINITY; int bi = 0;
            #pragma unroll
            for (int j = 0; j < LL; j++)
                if (!used[j] && d[j] > best) { best = d[j]; bi = j; }
            used[bi] = true;
            sh_idx[t][k] = bi;
        }
    }
    __syncthreads();

    // EdgeConv + BN + leaky + max over k -> e[o][l]
    for (int item = t; item < LL * C4; item += 256) {
        const int o = item & 63;
        const int l = item >> 6;
        const float* w1 = W_edge + o * (2 * C4);
        const float* w2 = w1 + C4;
        const int n0 = sh_idx[l][0], n1 = sh_idx[l][1], n2 = sh_idx[l][2];
        float base = 0.f, a0 = 0.f, a1 = 0.f, a2 = 0.f;
        #pragma unroll 4
        for (int c = 0; c < C4; c++) {
            const float w = w1[c];
            base += (w2[c] - w) * sh_s[c][l];
            a0 += w * sh_s[c][n0];
            a1 += w * sh_s[c][n1];
            a2 += w * sh_s[c][n2];
        }
        const float gs  = g_edge[o] * rsqrtf(v_edge[o] + EPS);
        const float shb = be_edge[o] - m_edge[o] * gs;
        float m = -INFINITY;
        float ys[3] = {a0 + base, a1 + base, a2 + base};
        #pragma unroll
        for (int k = 0; k < 3; k++) {
            float y = ys[k] * gs + shb;
            y = fmaxf(y, 0.f) + SLOPE * fminf(y, 0.f);
            m = fmaxf(m, y);
        }
        sh_e[o][l] = m;
    }
    __syncthreads();

    // att = W_agg @ e + b_agg ; gate = sigmoid
    {
        const int oc = t;                      // 256 threads == C outputs
        float a[LL];
        const float bb = b_agg[oc];
        #pragma unroll
        for (int l = 0; l < LL; l++) a[l] = bb;
        const float* wr = W_agg + oc * C4;
        #pragma unroll 4
        for (int c = 0; c < C4; c++) {
            const float w = wr[c];
            #pragma unroll
            for (int l = 0; l < LL; l++) a[l] += w * sh_e[c][l];
        }
        float* gp = g_gate + ((size_t)n * CC + oc) * LL;
        #pragma unroll
        for (int l = 0; l < LL; l++)
            gp[l] = 1.f / (1.f + expf(-a[l]));
    }
}

// ---------------------------------------------------------------------------
// Kernel 4: out[n,c,t,v] = sum_l x[n,c,l,t,v] * gate[n,c,l]   (float4)
// ---------------------------------------------------------------------------
__global__ __launch_bounds__(256) void k_gatesum(const float* __restrict__ x,
                                                 float* __restrict__ out) {
    const int gid = blockIdx.x * 256 + threadIdx.x;     // [0, 32*256*400)
    const int tv4 = gid % 400;
    const int nc  = gid / 400;
    const float4* xb = reinterpret_cast<const float4*>(x) + (size_t)nc * (LL * 400) + tv4;
    const float* gp = g_gate + (size_t)nc * LL;
    float4 acc = make_float4(0.f, 0.f, 0.f, 0.f);
    #pragma unroll
    for (int l = 0; l < LL; l++) {
        const float g = gp[l];
        const float4 xv = xb[l * 400];
        acc.x += xv.x * g; acc.y += xv.y * g;
        acc.z += xv.z * g; acc.w += xv.w * g;
    }
    reinterpret_cast<float4*>(out)[(size_t)nc * 400 + tv4] = acc;
}

// ---------------------------------------------------------------------------
extern "C" void kernel_launch(void* const* d_in, const int* in_sizes, int n_in,
                              void* d_out, int out_size) {
    const float* x       = (const float*)d_in[0];
    const float* W_down  = (const float*)d_in[1];
    const float* b_down  = (const float*)d_in[2];
    const float* g_down  = (const float*)d_in[3];
    const float* be_down = (const float*)d_in[4];
    const float* m_down  = (const float*)d_in[5];
    const float* v_down  = (const float*)d_in[6];
    const float* W_edge  = (const float*)d_in[7];
    const float* g_edge  = (const float*)d_in[8];
    const float* be_edge = (const float*)d_in[9];
    const float* m_edge  = (const float*)d_in[10];
    const float* v_edge  = (const float*)d_in[11];
    const float* W_agg   = (const float*)d_in[12];
    const float* b_agg   = (const float*)d_in[13];
    float* out = (float*)d_out;

    k_tmax<<<NB * CC * LL, 128>>>(x);
    k_s<<<NB * LL, 256>>>(W_down, b_down, g_down, be_down, m_down, v_down);
    k_mid<<<NB, 256>>>(W_edge, g_edge, be_edge, m_edge, v_edge, W_agg, b_agg);
    k_gatesum<<<(NB * CC * 400) / 256, 256>>>(x, out);
}